// round 17
// baseline (speedup 1.0000x reference)
#include <cuda_runtime.h>
#include <math.h>
#include <stdint.h>

#define NB      16
#define LSEQ    2048
#define NV      10
#define NPH     19
#define NCLS    190
#define NCLSP   192
#define NBUCK   3
#define CH64    64
#define TAB_TOTAL (NCLS * NBUCK * NCLSP)          // 109440
#define GRID    (NB * 32)                         // 512 blocks of 64 rows
#define NT      512

// ---------------- device scratch (static, allocation-free) ----------------
__device__ int g_P [NB * 64 * NCLSP];             // exclusive 32-gran prefix (within half)
__device__ int g_T0[NB * NCLSP];                  // per-class total of half 0
__device__ int g_t1[NB * NCLS];
__device__ int g_t2[NB * NCLS];
__device__ __align__(16) float2 g_tab[TAB_TOTAL]; // {e, e*vv0} per (q,bucket,cls)
__device__ unsigned g_bar = 0;                    // monotonic grid-barrier ticket

// ---------------- fp32 constants (no fp64 anywhere) ----------------
__device__ __forceinline__ float omega_f() { return 6.28318530717958647692f / 19.0f; }
// cancellation-free: cos(.3w)-cos(.7w) = 2 sin(.5w) sin(.2w); ATTN_SCALE = amp/2
__device__ __forceinline__ float asf_f() {
    float om = omega_f();
    return 2.302585092994046f / (4.0f * sinf(0.5f * om) * sinf(0.2f * om));
}
__device__ __forceinline__ float cosm_f(int m) {   // cos(om*m - phi), phi = om*10.3
    return cosf(omega_f() * ((float)m - 10.3f));
}
__device__ __forceinline__ float s_of(int d, float c, float e) {
    float h0 = c - e * (float)(d * d);
    float h1 = -(float)d;
    float r  = rsqrtf((h0 * h0 + h1 * h1) * 0.5f + 1e-6f);
    float hn0 = h0 * r;
    return hn0 * rsqrtf(hn0 * hn0 * 0.5f + 1e-6f);
}
__device__ __forceinline__ float vv0_of(int d, float c, float e, float v) {
    float h0 = c - e * (float)(d * d);
    float h1 = -(float)d;
    float r  = rsqrtf((h0 * h0 + h1 * h1) * 0.5f + 1e-6f);
    return h1 * r * v;
}

// ---------------- fused kernel: prep (phase A) + grid barrier + softmax (B) ----
__global__ void __launch_bounds__(NT, 4) k_fused(
    const int*   __restrict__ tokens,
    const float* __restrict__ C,        const float* __restrict__ eps,
    const float* __restrict__ v,
    const float* __restrict__ o_scale,  const float* __restrict__ g_base,
    const float* __restrict__ g_slope,  const float* __restrict__ carry_amp,
    float* __restrict__ out)
{
    extern __shared__ uint16_t cnt_sh[];   // phase B: [CH64][NCLSP] cumulative counts
    int* scratch = (int*)cnt_sh;           // phase A scratch (6144 ints)
    __shared__ int   tok_sh[CH64];
    __shared__ int   cls_sh[CH64];
    __shared__ int   t1S[NCLS], t2S[NCLS];
    __shared__ float sdf[NV], cmf[NPH];

    int bid = blockIdx.x, tid = threadIdx.x;
    int b   = bid >> 5;
    int ch  = bid & 31;                     // 64-row chunk index
    int T0  = ch * CH64;

    float c  = C[0], ee = eps[0];

    // tokens/classes for phase B (independent of prep, overlaps phase A)
    if (tid < CH64) {
        int tk = tokens[b * LSEQ + T0 + tid];
        tok_sh[tid] = tk;
        cls_sh[tid] = tk + 10 * ((T0 + tid) % NPH);
    }

    // ================= phase A: distributed prep =================
    if (bid < NB) {
        // ---- bucket thresholds for batch `bid` ----
        int* foS = scratch;
        int* tt1 = scratch + 256;
        int* tt2 = scratch + 512;
        if (tid < NCLSP) foS[tid] = 1 << 20;
        if (tid < NV)    sdf[tid] = s_of(tid, c, ee);
        if (tid < NPH)   cmf[tid] = cosm_f(tid);
        if (tid < NCLS)  { tt1[tid] = 1 << 28; tt2[tid] = 1 << 28; }
        __syncthreads();
        int4 tv = ((const int4*)(tokens + bid * LSEQ))[tid];
        int s0 = tid * 4;
        atomicMin(&foS[tv.x + 10 * ( s0      % NPH)], s0);
        atomicMin(&foS[tv.y + 10 * ((s0 + 1) % NPH)], s0 + 1);
        atomicMin(&foS[tv.z + 10 * ((s0 + 2) % NPH)], s0 + 2);
        atomicMin(&foS[tv.w + 10 * ((s0 + 3) % NPH)], s0 + 3);
        __syncthreads();
        float A = asf_f();
        for (int task = tid; task < NCLS * NPH; task += NT) {
            int q = task / NPH, p = task % NPH;
            int m = q % NPH - p; if (m < 0) m += NPH;
            float base = A * sdf[q / NPH] * cmf[m];
            int l1 = 1 << 28, l2 = 1 << 28;
            #pragma unroll
            for (int d = 0; d < NV; d++) {
                float L = base * sdf[d];
                int f = foS[d + 10 * p];
                if (L >= -6.0f)  l1 = min(l1, f);
                if (L >=  94.0f) l2 = min(l2, f);
            }
            atomicMin(&tt1[q], l1);
            atomicMin(&tt2[q], l2);
        }
        __syncthreads();
        if (tid < NCLS) {
            g_t1[bid * NCLS + tid] = tt1[tid];
            g_t2[bid * NCLS + tid] = tt2[tid];
        }
    } else if (bid < NB + 32) {
        // ---- histograms + exclusive 32-gran prefixes for half a batch ----
        int bx = bid - NB, hb = bx >> 1, half = bx & 1;
        int* hist = scratch;                 // [32][NCLSP] = 24576 B (exact fit)
        for (int i = tid; i < 32 * NCLSP; i += NT) hist[i] = 0;
        __syncthreads();
        int s0 = half * 1024 + tid;          // two positions per thread
        int c0 = tokens[hb * LSEQ + s0]       + 10 * ( s0        % NPH);
        int c1 = tokens[hb * LSEQ + s0 + NT]  + 10 * ((s0 + NT)  % NPH);
        atomicAdd(&hist[ (tid >> 5)       * NCLSP + c0], 1);
        atomicAdd(&hist[((tid >> 5) + 16) * NCLSP + c1], 1);
        __syncthreads();
        if (tid < NCLSP) {
            int run  = 0;
            int base = (hb * 64 + half * 32) * NCLSP + tid;
            #pragma unroll 4
            for (int sub = 0; sub < 32; sub++) {
                g_P[base + sub * NCLSP] = run;
                run += hist[sub * NCLSP + tid];
            }
            if (half == 0) g_T0[hb * NCLSP + tid] = run;
        }
    } else if (bid < NB + 32 + 107) {
        // ---- exp table: 1024 entries per block, 2 per thread ----
        int base_i = (bid - NB - 32) * 1024 + tid;
        #pragma unroll
        for (int rep = 0; rep < 2; rep++) {
            int idx = base_i + rep * NT;
            if (idx < TAB_TOTAL) {
                int cls    = idx % NCLSP;
                int rest   = idx / NCLSP;
                int bucket = rest % NBUCK;
                int q      = rest / NBUCK;
                float2 r = make_float2(0.f, 0.f);
                if (cls < NCLS) {
                    int dt = q / NPH, tp = q % NPH;
                    int d  = cls % 10, p = cls / 10;
                    int m  = tp - p; if (m < 0) m += NPH;
                    float vd  = v[0];
                    float L   = asf_f() * s_of(dt, c, ee) * s_of(d, c, ee) * cosm_f(m);
                    float off = -56.0f + 100.0f * (float)bucket;
                    float x   = expf(fminf(L - off, 60.0f)); // count-0 entries only
                    r = make_float2(x, x * vv0_of(d, c, ee, vd));
                }
                g_tab[idx] = r;
            }
        }
    }

    // ================= grid barrier (ticket-window, no reset) =================
    // All 512 blocks co-resident (4 blocks/SM x 148 SMs = 592 slots) -> safe.
    __syncthreads();
    __threadfence();
    if (tid == 0) {
        unsigned t = atomicAdd(&g_bar, 1u);
        unsigned target = (t & ~511u) + 512u;
        while (*(volatile unsigned*)&g_bar < target) __nanosleep(64);
        __threadfence();
    }
    __syncthreads();

    // ================= phase B: cumulative-histogram softmax =================
    // count scan: 384 threads, one 32-row quarter each
    if (tid < 384) {
        int grp = tid / NCLSP, cl = tid % NCLSP;
        int sg  = ch * 2 + grp;                  // global 32-subchunk index (0..63)
        int cnt = g_P[(b * 64 + sg) * NCLSP + cl];
        if (ch >= 16) cnt += g_T0[b * NCLSP + cl];
        int p0 = grp * 32;
        #pragma unroll 8
        for (int p = p0; p < p0 + 32; p++) {
            cnt += (cls_sh[p] == cl);
            cnt_sh[p * NCLSP + cl] = (uint16_t)cnt;
        }
    } else {
        int i = tid - 384;                       // 128 threads: thresholds
        for (int q = i; q < NCLS; q += 128) {
            t1S[q] = g_t1[b * NCLS + q];
            t2S[q] = g_t2[b * NCLS + q];
        }
    }
    __syncthreads();

    float osc = o_scale[0];
    float ga  = g_base[0], gc = g_slope[0], ca = carry_amp[0];

    int w    = tid >> 5, lane = tid & 31;        // 16 warps, 4 rows each
    int half = lane >> 4, ll = lane & 15;        // 2 rows per warp-iteration
    const uint32_t* cnt32 = (const uint32_t*)cnt_sh;

    float attnv[2];
    int   dtv[2];

    #pragma unroll
    for (int it = 0; it < 2; it++) {
        int r  = w * 4 + it * 2 + half;
        int t  = T0 + r;
        int dt = tok_sh[r];
        int q  = dt * NPH + (t % NPH);
        int bucket = (t >= t1S[q]) + (t >= t2S[q]);
        const float4* Tb = (const float4*)(g_tab + (q * NBUCK + bucket) * NCLSP);
        int cbase = r * (NCLSP / 2);
        dtv[it] = dt;

        float4 ea0 = __ldg(Tb + ll * 2);
        float4 eb0 = __ldg(Tb + ll * 2 + 1);
        float4 ea1 = __ldg(Tb + 32 + ll * 2);
        float4 eb1 = __ldg(Tb + 32 + ll * 2 + 1);
        float4 ea2 = __ldg(Tb + 64 + ll * 2);
        float4 eb2 = __ldg(Tb + 64 + ll * 2 + 1);
        uint2  u0  = *(const uint2*)(cnt32 + cbase      + ll * 2);
        uint2  u1  = *(const uint2*)(cnt32 + cbase + 32 + ll * 2);
        uint2  u2  = *(const uint2*)(cnt32 + cbase + 64 + ll * 2);

        float den, num;
        {
            float c0 = (float)(u0.x & 0xffff), c1 = (float)(u0.x >> 16);
            float c2 = (float)(u0.y & 0xffff), c3 = (float)(u0.y >> 16);
            den  = c0 * ea0.x + c1 * ea0.z + c2 * eb0.x + c3 * eb0.z;
            num  = c0 * ea0.y + c1 * ea0.w + c2 * eb0.y + c3 * eb0.w;
            c0 = (float)(u1.x & 0xffff); c1 = (float)(u1.x >> 16);
            c2 = (float)(u1.y & 0xffff); c3 = (float)(u1.y >> 16);
            den += c0 * ea1.x + c1 * ea1.z + c2 * eb1.x + c3 * eb1.z;
            num += c0 * ea1.y + c1 * ea1.w + c2 * eb1.y + c3 * eb1.w;
            c0 = (float)(u2.x & 0xffff); c1 = (float)(u2.x >> 16);
            c2 = (float)(u2.y & 0xffff); c3 = (float)(u2.y >> 16);
            den += c0 * ea2.x + c1 * ea2.z + c2 * eb2.x + c3 * eb2.z;
            num += c0 * ea2.y + c1 * ea2.w + c2 * eb2.y + c3 * eb2.w;
        }
        #pragma unroll
        for (int o = 8; o; o >>= 1) {            // 4-level butterfly within half
            den += __shfl_xor_sync(0xffffffffu, den, o);
            num += __shfl_xor_sync(0xffffffffu, num, o);
        }
        attnv[it] = __fdividef(num, den);
    }

    // deferred epilogues: two independent chains, full ILP
    #pragma unroll
    for (int it = 0; it < 2; it++) {
        int t  = T0 + w * 4 + it * 2 + half;
        int dt = dtv[it];
        float h0 = c - ee * (float)(dt * dt);
        float h1 = -(float)dt + osc * attnv[it];
        float rn = rsqrtf((h0 * h0 + h1 * h1) * 0.5f + 1e-6f);
        float hn0 = h0 * rn, hn1 = h1 * rn;
        float g0  = hn0 * ga + hn1 * gc;
        float g1  = hn0 * (ga - gc / c) + hn1 * gc;
        float carry = ca * (fmaxf(g1, 0.f) * hn0 - fmaxf(g0, 0.f) * hn0);
        float h1c = h1 + carry;
        float r2  = rsqrtf((h0 * h0 + h1c * h1c) * 0.5f + 1e-6f);
        const float inv_cn = 0.7071067811865475f;      // 1/sqrt(MODEL_DIM)
        float a0o = h0  * r2 * (0.1f * c * inv_cn);
        float a1o = h1c * r2 * (-c * 0.02f * inv_cn);  // -c/(50*sqrt2)
        if (ll < NV) {
            float t0  = c - ee * (float)(ll * ll);
            float t1v = -(float)ll;
            out[(b * LSEQ + t) * NV + ll] = a0o * t0 + a1o * t1v;
        }
    }
}

// ---------------- launch ----------------
extern "C" void kernel_launch(void* const* d_in, const int* in_sizes, int n_in,
                              void* d_out, int out_size) {
    const int*   tokens    = (const int*)  d_in[0];
    const float* C         = (const float*)d_in[1];
    const float* eps       = (const float*)d_in[2];
    const float* v         = (const float*)d_in[3];
    const float* o_scale   = (const float*)d_in[4];
    const float* g_base    = (const float*)d_in[5];
    const float* g_slope   = (const float*)d_in[6];
    const float* carry_amp = (const float*)d_in[7];
    float* out = (float*)d_out;

    const int smem = CH64 * NCLSP * (int)sizeof(uint16_t);   // 24576
    cudaFuncSetAttribute(k_fused, cudaFuncAttributeMaxDynamicSharedMemorySize, smem);

    k_fused<<<GRID, NT, smem>>>(tokens, C, eps, v, o_scale, g_base, g_slope,
                                carry_amp, out);
}